// round 12
// baseline (speedup 1.0000x reference)
#include <cuda_runtime.h>
#include <cstdint>

// ---------------------------------------------------------------------------
// EarthAttention3D: B=256 windows, N=144 tokens, DIM=384, H=12 heads, hd=32
//   1) QKV = x @ w_qkv + b_qkv   -> scatter to Q(scaled)/K/V in (b,h,n,d)
//   2) per (b,h): S = Q K^T + bias_gather + mask; P = softmax(S); O = P V
//   3) out = O @ w_out + b_out
// GEMMs in tf32 mma.sync (fp32 accumulate); attention fp32.
// ---------------------------------------------------------------------------

#define B_WIN   256
#define NTOK    144
#define DIM     384
#define HEADS   12
#define HD      32
#define QKV_N   1152
#define MROWS   (B_WIN * NTOK)        // 36864
#define QSCALE  0.17677669529663687f  // 32^-0.5

#define ELEMS   (B_WIN * HEADS * NTOK * HD)   // 14,155,776

__device__ float g_q[ELEMS];
__device__ float g_k[ELEMS];
__device__ float g_v[ELEMS];
__device__ float g_o[ELEMS];   // attention output (b, n, h*32+d) = (36864, 384)

__device__ __forceinline__ uint32_t f2tf(float f) {
    uint32_t u;
    asm("cvt.rna.tf32.f32 %0, %1;" : "=r"(u) : "f"(f));
    return u;
}

__device__ __forceinline__ void mma8(float* d, const uint32_t* a, const uint32_t* b) {
    asm volatile(
        "mma.sync.aligned.m16n8k8.row.col.f32.tf32.tf32.f32 "
        "{%0,%1,%2,%3}, {%4,%5,%6,%7}, {%8,%9}, {%0,%1,%2,%3};"
        : "+f"(d[0]), "+f"(d[1]), "+f"(d[2]), "+f"(d[3])
        : "r"(a[0]), "r"(a[1]), "r"(a[2]), "r"(a[3]),
          "r"(b[0]), "r"(b[1]));
}

// ---------------------------------------------------------------------------
// TF32 MMA GEMM: C(M,Nc) = A(M,K) @ B(K,Nc) + bias.
// BM=128 BN=128 BK=16, 256 threads = 8 warps, warp grid 2(m) x 4(n),
// warp tile 64x32 = 4x4 m16n8k8 tiles.
// MODE 0: scatter epilogue into g_q/g_k/g_v.  MODE 1: plain bias epilogue.
// Requires M%128==0, Nc%128==0, K%16==0 (true for all uses).
// ---------------------------------------------------------------------------
template <int MODE>
__global__ __launch_bounds__(256, 2)
void mma_gemm(const float* __restrict__ A, const float* __restrict__ B,
              const float* __restrict__ bias, float* __restrict__ C,
              int M, int Nc, int K)
{
    __shared__ __align__(16) uint32_t As[128][20];   // [m][k], pad 20 -> conflict-free frag loads
    __shared__ __align__(16) uint32_t Bs[16][136];   // [k][n], pad 136 -> conflict-free frag loads

    const int tid  = threadIdx.x;
    const int lane = tid & 31;
    const int wid  = tid >> 5;
    const int g    = lane >> 2;        // groupID
    const int c    = lane & 3;         // threadID_in_group
    const int wm   = wid >> 2;         // 0..1
    const int wn   = wid & 3;          // 0..3

    const int rowBase = blockIdx.y * 128;
    const int colBase = blockIdx.x * 128;

    // global->smem mapping
    const int am  = tid >> 2;          // 0..63 (+64 for second half)
    const int ak  = (tid & 3) * 4;
    const int bk  = tid >> 4;          // 0..15
    const int bn  = (tid & 15) * 4;    // 0..60 (+64 for second half)

    const float* Ap  = A + (size_t)(rowBase + am) * K + ak;
    const float* Ap2 = Ap + (size_t)64 * K;
    const float* Bp  = B + (size_t)bk * Nc + colBase + bn;

    float acc[4][4][4];
    #pragma unroll
    for (int mt = 0; mt < 4; ++mt)
        #pragma unroll
        for (int nt = 0; nt < 4; ++nt)
            #pragma unroll
            for (int r = 0; r < 4; ++r) acc[mt][nt][r] = 0.0f;

    for (int k0 = 0; k0 < K; k0 += 16) {
        float4 a0 = *(const float4*)(Ap  + k0);
        float4 a1 = *(const float4*)(Ap2 + k0);
        float4 b0 = *(const float4*)(Bp + (size_t)k0 * Nc);
        float4 b1 = *(const float4*)(Bp + (size_t)k0 * Nc + 64);
        __syncthreads();
        {
            uint4 u;
            u.x = f2tf(a0.x); u.y = f2tf(a0.y); u.z = f2tf(a0.z); u.w = f2tf(a0.w);
            *(uint4*)&As[am][ak] = u;
            u.x = f2tf(a1.x); u.y = f2tf(a1.y); u.z = f2tf(a1.z); u.w = f2tf(a1.w);
            *(uint4*)&As[am + 64][ak] = u;
            u.x = f2tf(b0.x); u.y = f2tf(b0.y); u.z = f2tf(b0.z); u.w = f2tf(b0.w);
            *(uint4*)&Bs[bk][bn] = u;
            u.x = f2tf(b1.x); u.y = f2tf(b1.y); u.z = f2tf(b1.z); u.w = f2tf(b1.w);
            *(uint4*)&Bs[bk][bn + 64] = u;
        }
        __syncthreads();

        #pragma unroll
        for (int ks = 0; ks < 2; ++ks) {
            const int kb = ks * 8;
            uint32_t af[4][4];
            #pragma unroll
            for (int mt = 0; mt < 4; ++mt) {
                const int m = wm * 64 + mt * 16;
                af[mt][0] = As[m + g    ][kb + c];
                af[mt][1] = As[m + g + 8][kb + c];
                af[mt][2] = As[m + g    ][kb + c + 4];
                af[mt][3] = As[m + g + 8][kb + c + 4];
            }
            uint32_t bf[4][2];
            #pragma unroll
            for (int nt = 0; nt < 4; ++nt) {
                const int n = wn * 32 + nt * 8 + g;
                bf[nt][0] = Bs[kb + c    ][n];
                bf[nt][1] = Bs[kb + c + 4][n];
            }
            #pragma unroll
            for (int mt = 0; mt < 4; ++mt)
                #pragma unroll
                for (int nt = 0; nt < 4; ++nt)
                    mma8(acc[mt][nt], af[mt], bf[nt]);
        }
    }

    if (MODE == 0) {
        // block never straddles a 384-column boundary (colBase%384 in {0,128,256})
        const int which = colBase / 384;
        float* dst = (which == 0) ? g_q : ((which == 1) ? g_k : g_v);
        const float mul = (which == 0) ? QSCALE : 1.0f;
        const int remBase = colBase - which * 384 + wn * 32;
        #pragma unroll
        for (int mt = 0; mt < 4; ++mt) {
            const int r0  = rowBase + wm * 64 + mt * 16 + g;
            const int r1  = r0 + 8;
            const int bb0 = r0 / NTOK, nn0 = r0 - bb0 * NTOK;
            const int bb1 = r1 / NTOK, nn1 = r1 - bb1 * NTOK;
            #pragma unroll
            for (int nt = 0; nt < 4; ++nt) {
                const int rem = remBase + nt * 8 + 2 * c;   // even, pair stays in one head
                const int hh = rem >> 5, dd = rem & 31;
                const float2 bv = *(const float2*)&bias[which * 384 + rem];
                const size_t o0 = ((size_t)(bb0 * HEADS + hh) * NTOK + nn0) * HD + dd;
                const size_t o1 = ((size_t)(bb1 * HEADS + hh) * NTOK + nn1) * HD + dd;
                float2 v0, v1;
                v0.x = (acc[mt][nt][0] + bv.x) * mul;
                v0.y = (acc[mt][nt][1] + bv.y) * mul;
                v1.x = (acc[mt][nt][2] + bv.x) * mul;
                v1.y = (acc[mt][nt][3] + bv.y) * mul;
                *(float2*)&dst[o0] = v0;
                *(float2*)&dst[o1] = v1;
            }
        }
    } else {
        #pragma unroll
        for (int mt = 0; mt < 4; ++mt) {
            const int r0 = rowBase + wm * 64 + mt * 16 + g;
            #pragma unroll
            for (int nt = 0; nt < 4; ++nt) {
                const int col = colBase + wn * 32 + nt * 8 + 2 * c;
                const float2 bv = *(const float2*)&bias[col];
                float2 v0, v1;
                v0.x = acc[mt][nt][0] + bv.x;  v0.y = acc[mt][nt][1] + bv.y;
                v1.x = acc[mt][nt][2] + bv.x;  v1.y = acc[mt][nt][3] + bv.y;
                *(float2*)&C[(size_t)r0 * Nc + col]       = v0;
                *(float2*)&C[(size_t)(r0 + 8) * Nc + col] = v1;
            }
        }
    }
}

// ---------------------------------------------------------------------------
// Fused attention: one block per (b,h), 256 threads (16x16).
// smem: Qs[144][33], Kt[32][145], Vs[144][33], Ps[48][144], bval[2592]
// Bias values (only 2592 distinct per block, row period 18) are gathered ONCE
// into smem instead of per-element LDG.
// ---------------------------------------------------------------------------
#define ATTN_SMEM ((144*33 + 32*145 + 144*33 + 48*144) * 4 + 2592 * 4)  // 94592 B

__global__ __launch_bounds__(256)
void attn_kernel(const float* __restrict__ mask,
                 const float* __restrict__ bias_table,
                 const int*   __restrict__ pos_index)
{
    extern __shared__ float sm[];
    float* Qs   = sm;                       // 144*33
    float* Kt   = Qs + 144 * 33;            // 32*145
    float* Vs   = Kt + 32 * 145;            // 144*33
    float* Ps   = Vs + 144 * 33;            // 48*144
    float* bval = Ps + 48 * 144;            // 2592

    const int bh = blockIdx.x;
    const int b  = bh / HEADS;
    const int h  = bh - b * HEADS;
    const int tid = threadIdx.x;
    const int tx = tid & 15;
    const int ty = tid >> 4;

    const float* qp = g_q + (size_t)bh * (NTOK * HD);
    const float* kp = g_k + (size_t)bh * (NTOK * HD);
    const float* vp = g_v + (size_t)bh * (NTOK * HD);

    for (int i = tid; i < NTOK * HD; i += 256) {
        const int n = i >> 5, d = i & 31;
        Qs[n * 33 + d]  = qp[i];
        Kt[d * 145 + n] = kp[i];
        Vs[n * 33 + d]  = vp[i];
    }
    {
        const int w  = b >> 5;                       // position-index replica
        const int tc = (b & 31) * HEADS + h;         // table column
        for (int a = tid; a < 2592; a += 256)
            bval[a] = __ldg(bias_table + pos_index[a * 8 + w] * (32 * HEADS) + tc);
    }
    __syncthreads();

    const float* mrow = mask + (size_t)(b & 7) * (NTOK * NTOK);
    float* op = g_o + (size_t)b * NTOK * DIM + h * HD;

    for (int panel = 0; panel < 3; ++panel) {
        const int rbase = panel * 48;
        const int r0 = rbase + ty * 3;

        float acc[3][9];
        #pragma unroll
        for (int r = 0; r < 3; ++r)
            #pragma unroll
            for (int c = 0; c < 9; ++c) acc[r][c] = 0.0f;

        // S = Q K^T
        #pragma unroll 8
        for (int d = 0; d < 32; ++d) {
            const float a0 = Qs[(r0 + 0) * 33 + d];
            const float a1 = Qs[(r0 + 1) * 33 + d];
            const float a2 = Qs[(r0 + 2) * 33 + d];
            #pragma unroll
            for (int c = 0; c < 9; ++c) {
                const float kv = Kt[d * 145 + tx * 9 + c];
                acc[0][c] += a0 * kv;
                acc[1][c] += a1 * kv;
                acc[2][c] += a2 * kv;
            }
        }

        // + earth bias (smem-cached gather) + mask
        #pragma unroll
        for (int r = 0; r < 3; ++r) {
            const int i  = r0 + r;
            const int im = i % 18;
            const float* brow = bval + im * NTOK;
            const float* mr   = mrow + (size_t)i * NTOK;
            #pragma unroll
            for (int c = 0; c < 9; ++c) {
                const int j = tx * 9 + c;
                acc[r][c] += brow[j] + mr[j];
            }
        }

        // softmax across the 16 tx lanes (width-16 shfl segments)
        #pragma unroll
        for (int r = 0; r < 3; ++r) {
            float mx = acc[r][0];
            #pragma unroll
            for (int c = 1; c < 9; ++c) mx = fmaxf(mx, acc[r][c]);
            #pragma unroll
            for (int o = 8; o >= 1; o >>= 1)
                mx = fmaxf(mx, __shfl_xor_sync(0xffffffffu, mx, o, 16));
            float s = 0.0f;
            #pragma unroll
            for (int c = 0; c < 9; ++c) {
                const float e = __expf(acc[r][c] - mx);
                acc[r][c] = e;
                s += e;
            }
            #pragma unroll
            for (int o = 8; o >= 1; o >>= 1)
                s += __shfl_xor_sync(0xffffffffu, s, o, 16);
            const float inv = 1.0f / s;
            #pragma unroll
            for (int c = 0; c < 9; ++c)
                Ps[(ty * 3 + r) * NTOK + tx * 9 + c] = acc[r][c] * inv;
        }
        __syncthreads();

        // O = P V  (3 rows x 2 cols per thread)
        float o00 = 0, o01 = 0, o10 = 0, o11 = 0, o20 = 0, o21 = 0;
        #pragma unroll 4
        for (int k = 0; k < NTOK; ++k) {
            const float v0 = Vs[k * 33 + tx * 2 + 0];
            const float v1 = Vs[k * 33 + tx * 2 + 1];
            const float p0 = Ps[(ty * 3 + 0) * NTOK + k];
            const float p1 = Ps[(ty * 3 + 1) * NTOK + k];
            const float p2 = Ps[(ty * 3 + 2) * NTOK + k];
            o00 += p0 * v0;  o01 += p0 * v1;
            o10 += p1 * v0;  o11 += p1 * v1;
            o20 += p2 * v0;  o21 += p2 * v1;
        }
        {
            const size_t rw = (size_t)(rbase + ty * 3) * DIM + tx * 2;
            op[rw + 0 * DIM + 0] = o00;  op[rw + 0 * DIM + 1] = o01;
            op[rw + 1 * DIM + 0] = o10;  op[rw + 1 * DIM + 1] = o11;
            op[rw + 2 * DIM + 0] = o20;  op[rw + 2 * DIM + 1] = o21;
        }
        __syncthreads();
    }
}

// ---------------------------------------------------------------------------
extern "C" void kernel_launch(void* const* d_in, const int* in_sizes, int n_in,
                              void* d_out, int out_size)
{
    const float* x      = (const float*)d_in[0];
    const float* mask   = (const float*)d_in[1];
    const float* w_qkv  = (const float*)d_in[2];
    const float* b_qkv  = (const float*)d_in[3];
    const float* w_out  = (const float*)d_in[4];
    const float* b_out  = (const float*)d_in[5];
    const float* btab   = (const float*)d_in[6];
    const int*   pidx   = (const int*)d_in[7];
    float* out = (float*)d_out;

    float* go = nullptr;
    cudaGetSymbolAddress((void**)&go, g_o);

    // 1) QKV projection (tf32 mma) with fused scatter + q-scale
    {
        dim3 grid(QKV_N / 128, MROWS / 128);   // (9, 288)
        mma_gemm<0><<<grid, 256>>>(x, w_qkv, b_qkv, nullptr, MROWS, QKV_N, DIM);
    }

    // 2) fused attention (bias gather + mask + softmax + PV)
    {
        cudaFuncSetAttribute(attn_kernel,
                             cudaFuncAttributeMaxDynamicSharedMemorySize,
                             ATTN_SMEM);
        attn_kernel<<<B_WIN * HEADS, 256, ATTN_SMEM>>>(mask, btab, pidx);
    }

    // 3) output projection (tf32 mma)
    {
        dim3 grid(DIM / 128, MROWS / 128);     // (3, 288)
        mma_gemm<1><<<grid, 256>>>(go, w_out, b_out, out, MROWS, DIM, DIM);
    }
}

// round 15
// speedup vs baseline: 1.0105x; 1.0105x over previous
#include <cuda_runtime.h>
#include <cstdint>

// ---------------------------------------------------------------------------
// EarthAttention3D: B=256 windows, N=144 tokens, DIM=384, H=12 heads, hd=32
//   1) QKV = x @ w_qkv + b_qkv   -> scatter to Q(scaled)/K/V in (b,h,n,d)
//   2) per (b,h): S = Q K^T + bias_gather + mask; P = softmax(S); O = P V
//   3) out = O @ w_out + b_out
// GEMMs in tf32 mma.sync (fp32 accumulate); attention fp32.
// ---------------------------------------------------------------------------

#define B_WIN   256
#define NTOK    144
#define DIM     384
#define HEADS   12
#define HD      32
#define QKV_N   1152
#define MROWS   (B_WIN * NTOK)        // 36864
#define QSCALE  0.17677669529663687f  // 32^-0.5

#define ELEMS   (B_WIN * HEADS * NTOK * HD)   // 14,155,776

__device__ float g_q[ELEMS];
__device__ float g_k[ELEMS];
__device__ float g_v[ELEMS];
__device__ float g_o[ELEMS];   // attention output (b, n, h*32+d) = (36864, 384)

__device__ __forceinline__ uint32_t f2tf(float f) {
    uint32_t u;
    asm("cvt.rna.tf32.f32 %0, %1;" : "=r"(u) : "f"(f));
    return u;
}

__device__ __forceinline__ void mma8(float* d, const uint32_t* a, const uint32_t* b) {
    asm volatile(
        "mma.sync.aligned.m16n8k8.row.col.f32.tf32.tf32.f32 "
        "{%0,%1,%2,%3}, {%4,%5,%6,%7}, {%8,%9}, {%0,%1,%2,%3};"
        : "+f"(d[0]), "+f"(d[1]), "+f"(d[2]), "+f"(d[3])
        : "r"(a[0]), "r"(a[1]), "r"(a[2]), "r"(a[3]),
          "r"(b[0]), "r"(b[1]));
}

// ---------------------------------------------------------------------------
// TF32 MMA GEMM: C(M,Nc) = A(M,K) @ B(K,Nc) + bias.
// BM=128 BN=128 BK=16, 256 threads = 8 warps, warp grid 2(m) x 4(n),
// warp tile 64x32 = 4x4 m16n8k8 tiles.
// MODE 0: scatter epilogue into g_q/g_k/g_v.  MODE 1: plain bias epilogue.
// Requires M%128==0, Nc%128==0, K%16==0 (true for all uses).
// ---------------------------------------------------------------------------
template <int MODE>
__global__ __launch_bounds__(256, 2)
void mma_gemm(const float* __restrict__ A, const float* __restrict__ B,
              const float* __restrict__ bias, float* __restrict__ C,
              int M, int Nc, int K)
{
    __shared__ __align__(16) uint32_t As[128][20];   // [m][k], pad 20 -> conflict-free frag loads
    __shared__ __align__(16) uint32_t Bs[16][136];   // [k][n], pad 136 -> conflict-free frag loads

    const int tid  = threadIdx.x;
    const int lane = tid & 31;
    const int wid  = tid >> 5;
    const int g    = lane >> 2;        // groupID
    const int c    = lane & 3;         // threadID_in_group
    const int wm   = wid >> 2;         // 0..1
    const int wn   = wid & 3;          // 0..3

    const int rowBase = blockIdx.y * 128;
    const int colBase = blockIdx.x * 128;

    // global->smem mapping
    const int am  = tid >> 2;          // 0..63 (+64 for second half)
    const int ak  = (tid & 3) * 4;
    const int bk  = tid >> 4;          // 0..15
    const int bn  = (tid & 15) * 4;    // 0..60 (+64 for second half)

    const float* Ap  = A + (size_t)(rowBase + am) * K + ak;
    const float* Ap2 = Ap + (size_t)64 * K;
    const float* Bp  = B + (size_t)bk * Nc + colBase + bn;

    float acc[4][4][4];
    #pragma unroll
    for (int mt = 0; mt < 4; ++mt)
        #pragma unroll
        for (int nt = 0; nt < 4; ++nt)
            #pragma unroll
            for (int r = 0; r < 4; ++r) acc[mt][nt][r] = 0.0f;

    for (int k0 = 0; k0 < K; k0 += 16) {
        float4 a0 = *(const float4*)(Ap  + k0);
        float4 a1 = *(const float4*)(Ap2 + k0);
        float4 b0 = *(const float4*)(Bp + (size_t)k0 * Nc);
        float4 b1 = *(const float4*)(Bp + (size_t)k0 * Nc + 64);
        __syncthreads();
        {
            uint4 u;
            u.x = f2tf(a0.x); u.y = f2tf(a0.y); u.z = f2tf(a0.z); u.w = f2tf(a0.w);
            *(uint4*)&As[am][ak] = u;
            u.x = f2tf(a1.x); u.y = f2tf(a1.y); u.z = f2tf(a1.z); u.w = f2tf(a1.w);
            *(uint4*)&As[am + 64][ak] = u;
            u.x = f2tf(b0.x); u.y = f2tf(b0.y); u.z = f2tf(b0.z); u.w = f2tf(b0.w);
            *(uint4*)&Bs[bk][bn] = u;
            u.x = f2tf(b1.x); u.y = f2tf(b1.y); u.z = f2tf(b1.z); u.w = f2tf(b1.w);
            *(uint4*)&Bs[bk][bn + 64] = u;
        }
        __syncthreads();

        #pragma unroll
        for (int ks = 0; ks < 2; ++ks) {
            const int kb = ks * 8;
            uint32_t af[4][4];
            #pragma unroll
            for (int mt = 0; mt < 4; ++mt) {
                const int m = wm * 64 + mt * 16;
                af[mt][0] = As[m + g    ][kb + c];
                af[mt][1] = As[m + g + 8][kb + c];
                af[mt][2] = As[m + g    ][kb + c + 4];
                af[mt][3] = As[m + g + 8][kb + c + 4];
            }
            uint32_t bf[4][2];
            #pragma unroll
            for (int nt = 0; nt < 4; ++nt) {
                const int n = wn * 32 + nt * 8 + g;
                bf[nt][0] = Bs[kb + c    ][n];
                bf[nt][1] = Bs[kb + c + 4][n];
            }
            #pragma unroll
            for (int mt = 0; mt < 4; ++mt)
                #pragma unroll
                for (int nt = 0; nt < 4; ++nt)
                    mma8(acc[mt][nt], af[mt], bf[nt]);
        }
    }

    if (MODE == 0) {
        // block never straddles a 384-column boundary (colBase%384 in {0,128,256})
        const int which = colBase / 384;
        float* dst = (which == 0) ? g_q : ((which == 1) ? g_k : g_v);
        const float mul = (which == 0) ? QSCALE : 1.0f;
        const int remBase = colBase - which * 384 + wn * 32;
        #pragma unroll
        for (int mt = 0; mt < 4; ++mt) {
            const int r0  = rowBase + wm * 64 + mt * 16 + g;
            const int r1  = r0 + 8;
            const int bb0 = r0 / NTOK, nn0 = r0 - bb0 * NTOK;
            const int bb1 = r1 / NTOK, nn1 = r1 - bb1 * NTOK;
            #pragma unroll
            for (int nt = 0; nt < 4; ++nt) {
                const int rem = remBase + nt * 8 + 2 * c;   // even, pair stays in one head
                const int hh = rem >> 5, dd = rem & 31;
                const float2 bv = *(const float2*)&bias[which * 384 + rem];
                const size_t o0 = ((size_t)(bb0 * HEADS + hh) * NTOK + nn0) * HD + dd;
                const size_t o1 = ((size_t)(bb1 * HEADS + hh) * NTOK + nn1) * HD + dd;
                float2 v0, v1;
                v0.x = (acc[mt][nt][0] + bv.x) * mul;
                v0.y = (acc[mt][nt][1] + bv.y) * mul;
                v1.x = (acc[mt][nt][2] + bv.x) * mul;
                v1.y = (acc[mt][nt][3] + bv.y) * mul;
                *(float2*)&dst[o0] = v0;
                *(float2*)&dst[o1] = v1;
            }
        }
    } else {
        #pragma unroll
        for (int mt = 0; mt < 4; ++mt) {
            const int r0 = rowBase + wm * 64 + mt * 16 + g;
            #pragma unroll
            for (int nt = 0; nt < 4; ++nt) {
                const int col = colBase + wn * 32 + nt * 8 + 2 * c;
                const float2 bv = *(const float2*)&bias[col];
                float2 v0, v1;
                v0.x = acc[mt][nt][0] + bv.x;  v0.y = acc[mt][nt][1] + bv.y;
                v1.x = acc[mt][nt][2] + bv.x;  v1.y = acc[mt][nt][3] + bv.y;
                *(float2*)&C[(size_t)r0 * Nc + col]       = v0;
                *(float2*)&C[(size_t)(r0 + 8) * Nc + col] = v1;
            }
        }
    }
}

// ---------------------------------------------------------------------------
// Fused attention: one block per (b,h), 256 threads (16x16).
// smem: Qs[144][33], Kt[32][145], Vs[144][33], Ps[48][144], bval[2592]
// Bias values (only 2592 distinct per block, row period 18) are gathered ONCE
// into smem instead of per-element LDG.
// ---------------------------------------------------------------------------
#define ATTN_SMEM ((144*33 + 32*145 + 144*33 + 48*144) * 4 + 2592 * 4)  // 94592 B

__global__ __launch_bounds__(256)
void attn_kernel(const float* __restrict__ mask,
                 const float* __restrict__ bias_table,
                 const int*   __restrict__ pos_index)
{
    extern __shared__ float sm[];
    float* Qs   = sm;                       // 144*33
    float* Kt   = Qs + 144 * 33;            // 32*145
    float* Vs   = Kt + 32 * 145;            // 144*33
    float* Ps   = Vs + 144 * 33;            // 48*144
    float* bval = Ps + 48 * 144;            // 2592

    const int bh = blockIdx.x;
    const int b  = bh / HEADS;
    const int h  = bh - b * HEADS;
    const int tid = threadIdx.x;
    const int tx = tid & 15;
    const int ty = tid >> 4;

    const float* qp = g_q + (size_t)bh * (NTOK * HD);
    const float* kp = g_k + (size_t)bh * (NTOK * HD);
    const float* vp = g_v + (size_t)bh * (NTOK * HD);

    for (int i = tid; i < NTOK * HD; i += 256) {
        const int n = i >> 5, d = i & 31;
        Qs[n * 33 + d]  = qp[i];
        Kt[d * 145 + n] = kp[i];
        Vs[n * 33 + d]  = vp[i];
    }
    {
        const int w  = b >> 5;                       // position-index replica
        const int tc = (b & 31) * HEADS + h;         // table column
        for (int a = tid; a < 2592; a += 256)
            bval[a] = __ldg(bias_table + pos_index[a * 8 + w] * (32 * HEADS) + tc);
    }
    __syncthreads();

    const float* mrow = mask + (size_t)(b & 7) * (NTOK * NTOK);
    float* op = g_o + (size_t)b * NTOK * DIM + h * HD;

    for (int panel = 0; panel < 3; ++panel) {
        const int rbase = panel * 48;
        const int r0 = rbase + ty * 3;

        float acc[3][9];
        #pragma unroll
        for (int r = 0; r < 3; ++r)
            #pragma unroll
            for (int c = 0; c < 9; ++c) acc[r][c] = 0.0f;

        // S = Q K^T
        #pragma unroll 8
        for (int d = 0; d < 32; ++d) {
            const float a0 = Qs[(r0 + 0) * 33 + d];
            const float a1 = Qs[(r0 + 1) * 33 + d];
            const float a2 = Qs[(r0 + 2) * 33 + d];
            #pragma unroll
            for (int c = 0; c < 9; ++c) {
                const float kv = Kt[d * 145 + tx * 9 + c];
                acc[0][c] += a0 * kv;
                acc[1][c] += a1 * kv;
                acc[2][c] += a2 * kv;
            }
        }

        // + earth bias (smem-cached gather) + mask
        #pragma unroll
        for (int r = 0; r < 3; ++r) {
            const int i  = r0 + r;
            const int im = i % 18;
            const float* brow = bval + im * NTOK;
            const float* mr   = mrow + (size_t)i * NTOK;
            #pragma unroll
            for (int c = 0; c < 9; ++c) {
                const int j = tx * 9 + c;
                acc[r][c] += brow[j] + mr[j];
            }
        }

        // softmax across the 16 tx lanes (width-16 shfl segments)
        #pragma unroll
        for (int r = 0; r < 3; ++r) {
            float mx = acc[r][0];
            #pragma unroll
            for (int c = 1; c < 9; ++c) mx = fmaxf(mx, acc[r][c]);
            #pragma unroll
            for (int o = 8; o >= 1; o >>= 1)
                mx = fmaxf(mx, __shfl_xor_sync(0xffffffffu, mx, o, 16));
            float s = 0.0f;
            #pragma unroll
            for (int c = 0; c < 9; ++c) {
                const float e = __expf(acc[r][c] - mx);
                acc[r][c] = e;
                s += e;
            }
            #pragma unroll
            for (int o = 8; o >= 1; o >>= 1)
                s += __shfl_xor_sync(0xffffffffu, s, o, 16);
            const float inv = 1.0f / s;
            #pragma unroll
            for (int c = 0; c < 9; ++c)
                Ps[(ty * 3 + r) * NTOK + tx * 9 + c] = acc[r][c] * inv;
        }
        __syncthreads();

        // O = P V  (3 rows x 2 cols per thread)
        float o00 = 0, o01 = 0, o10 = 0, o11 = 0, o20 = 0, o21 = 0;
        #pragma unroll 4
        for (int k = 0; k < NTOK; ++k) {
            const float v0 = Vs[k * 33 + tx * 2 + 0];
            const float v1 = Vs[k * 33 + tx * 2 + 1];
            const float p0 = Ps[(ty * 3 + 0) * NTOK + k];
            const float p1 = Ps[(ty * 3 + 1) * NTOK + k];
            const float p2 = Ps[(ty * 3 + 2) * NTOK + k];
            o00 += p0 * v0;  o01 += p0 * v1;
            o10 += p1 * v0;  o11 += p1 * v1;
            o20 += p2 * v0;  o21 += p2 * v1;
        }
        {
            const size_t rw = (size_t)(rbase + ty * 3) * DIM + tx * 2;
            op[rw + 0 * DIM + 0] = o00;  op[rw + 0 * DIM + 1] = o01;
            op[rw + 1 * DIM + 0] = o10;  op[rw + 1 * DIM + 1] = o11;
            op[rw + 2 * DIM + 0] = o20;  op[rw + 2 * DIM + 1] = o21;
        }
        __syncthreads();
    }
}

// ---------------------------------------------------------------------------
extern "C" void kernel_launch(void* const* d_in, const int* in_sizes, int n_in,
                              void* d_out, int out_size)
{
    const float* x      = (const float*)d_in[0];
    const float* mask   = (const float*)d_in[1];
    const float* w_qkv  = (const float*)d_in[2];
    const float* b_qkv  = (const float*)d_in[3];
    const float* w_out  = (const float*)d_in[4];
    const float* b_out  = (const float*)d_in[5];
    const float* btab   = (const float*)d_in[6];
    const int*   pidx   = (const int*)d_in[7];
    float* out = (float*)d_out;

    float* go = nullptr;
    cudaGetSymbolAddress((void**)&go, g_o);

    // 1) QKV projection (tf32 mma) with fused scatter + q-scale
    {
        dim3 grid(QKV_N / 128, MROWS / 128);   // (9, 288)
        mma_gemm<0><<<grid, 256>>>(x, w_qkv, b_qkv, nullptr, MROWS, QKV_N, DIM);
    }

    // 2) fused attention (bias gather + mask + softmax + PV)
    {
        cudaFuncSetAttribute(attn_kernel,
                             cudaFuncAttributeMaxDynamicSharedMemorySize,
                             ATTN_SMEM);
        attn_kernel<<<B_WIN * HEADS, 256, ATTN_SMEM>>>(mask, btab, pidx);
    }

    // 3) output projection (tf32 mma)
    {
        dim3 grid(DIM / 128, MROWS / 128);     // (3, 288)
        mma_gemm<1><<<grid, 256>>>(go, w_out, b_out, out, MROWS, DIM, DIM);
    }
}